// round 8
// baseline (speedup 1.0000x reference)
#include <cuda_runtime.h>
#include <math.h>

#define N_AUTH  50000
#define N_PAP   100000
#define N_TOT   150000
#define DD      128
#define NLAY    3
#define NEDGE   2400000
#define NEG_SLOPE 0.01f
#define EPSN    1e-12f

#define NBS     293          // scan blocks: ceil(150000/512)
#define SCH     512          // counts per scan block

// ---------------- static device scratch (no runtime alloc allowed) ----------
static __device__ float g_ego [N_TOT * DD];
static __device__ float g_side[N_TOT * DD];
static __device__ int   g_rowptr[N_TOT + 1];
static __device__ int   g_wptr  [N_TOT];
static __device__ int   g_cnt   [N_TOT];     // zero at module load; fill re-zeroes
static __device__ int   g_bsum  [NBS];
static __device__ int2  g_cv    [NEDGE];     // interleaved (col, val-bits)

// ---------------- helpers ----------------------------------------------------
__device__ __forceinline__ void fma2(unsigned long long& d,
                                     unsigned long long a,
                                     unsigned long long b) {
    asm("fma.rn.f32x2 %0, %1, %2, %0;" : "+l"(d) : "l"(a), "l"(b));
}
union U64F2 { unsigned long long u; float2 f; };

// ---------------- CSR build --------------------------------------------------
__global__ void count_kernel(const int* __restrict__ rows) {
    int i = blockIdx.x * blockDim.x + threadIdx.x;
    if (i < NEDGE) atomicAdd(&g_cnt[rows[i]], 1);
}

// stage 1: per-block sums of 512 counts
__global__ void scan1_kernel() {
    __shared__ int red[256];
    int b = blockIdx.x, t = threadIdx.x;
    int i0 = b * SCH + 2 * t;
    int v = 0;
    if (i0     < N_TOT) v += g_cnt[i0];
    if (i0 + 1 < N_TOT) v += g_cnt[i0 + 1];
    red[t] = v;
    __syncthreads();
    for (int o = 128; o > 0; o >>= 1) {
        if (t < o) red[t] += red[t + o];
        __syncthreads();
    }
    if (t == 0) g_bsum[b] = red[0];
}

// stage 2 (merged): each block computes its own bsum-prefix, then local scan
__global__ void scan3_kernel() {
    __shared__ int sh[256];
    int b = blockIdx.x, t = threadIdx.x;

    // exclusive block offset = sum of g_bsum[0..b)
    int acc = 0;
    for (int i = t; i < b; i += 256) acc += g_bsum[i];
    sh[t] = acc;
    __syncthreads();
    for (int o = 128; o > 0; o >>= 1) {
        if (t < o) sh[t] += sh[t + o];
        __syncthreads();
    }
    const int off = sh[0];
    __syncthreads();

    if (b == NBS - 1 && t == 0) g_rowptr[N_TOT] = off + g_bsum[b];

    // local exclusive scan of this block's 512 counts
    int i0 = b * SCH + 2 * t;
    int c0 = (i0     < N_TOT) ? g_cnt[i0]     : 0;
    int c1 = (i0 + 1 < N_TOT) ? g_cnt[i0 + 1] : 0;
    int pair = c0 + c1;
    sh[t] = pair;
    __syncthreads();
    for (int o = 1; o < 256; o <<= 1) {
        int x = (t >= o) ? sh[t - o] : 0;
        __syncthreads();
        sh[t] += x;
        __syncthreads();
    }
    int excl = sh[t] - pair + off;
    if (i0 < N_TOT)     { g_rowptr[i0]     = excl;      g_wptr[i0]     = excl; }
    if (i0 + 1 < N_TOT) { g_rowptr[i0 + 1] = excl + c0; g_wptr[i0 + 1] = excl + c0; }
}

// fill CSR (interleaved col/val) and re-zero g_cnt for the next call
__global__ void fill_kernel(const int* __restrict__ rows,
                            const int* __restrict__ cols,
                            const float* __restrict__ vals) {
    int i = blockIdx.x * blockDim.x + threadIdx.x;
    if (i < N_TOT) g_cnt[i] = 0;
    if (i < NEDGE) {
        int r = rows[i];
        int p = atomicAdd(&g_wptr[r], 1);
        g_cv[p] = make_int2(cols[i], __float_as_int(vals[i]));
    }
}

// ---------------- init -------------------------------------------------------
__global__ void init_kernel(const float* __restrict__ author,
                            const float* __restrict__ paper,
                            float* __restrict__ out) {
    int i = blockIdx.x * blockDim.x + threadIdx.x;
    if (i >= N_TOT * 32) return;
    int node = i >> 5;
    int c4   = (i & 31) * 4;
    float4 v;
    if (node < N_AUTH) v = *reinterpret_cast<const float4*>(author + node * DD + c4);
    else               v = *reinterpret_cast<const float4*>(paper + (node - N_AUTH) * DD + c4);
    *reinterpret_cast<float4*>(g_ego + node * DD + c4) = v;
    *reinterpret_cast<float4*>(out + (size_t)node * (4 * DD) + c4) = v;
}

// ---------------- SpMM: warp per row, 4 dims per lane, unroll-4, 4 accs ------
__global__ void spmm_kernel() {
    int gt   = blockIdx.x * blockDim.x + threadIdx.x;
    int row  = gt >> 5;
    int lane = gt & 31;
    if (row >= N_TOT) return;
    int s = g_rowptr[row];
    int e = g_rowptr[row + 1];
    const float* egoL = g_ego + lane * 4;
    float4 a0 = make_float4(0.f, 0.f, 0.f, 0.f);
    float4 a1 = a0, a2 = a0, a3 = a0;
    int i = s;
    for (; i + 3 < e; i += 4) {
        int2 q0 = g_cv[i];
        int2 q1 = g_cv[i + 1];
        int2 q2 = g_cv[i + 2];
        int2 q3 = g_cv[i + 3];
        float4 x0 = *reinterpret_cast<const float4*>(egoL + q0.x * DD);
        float4 x1 = *reinterpret_cast<const float4*>(egoL + q1.x * DD);
        float4 x2 = *reinterpret_cast<const float4*>(egoL + q2.x * DD);
        float4 x3 = *reinterpret_cast<const float4*>(egoL + q3.x * DD);
        float v0 = __int_as_float(q0.y);
        float v1 = __int_as_float(q1.y);
        float v2 = __int_as_float(q2.y);
        float v3 = __int_as_float(q3.y);
        a0.x += v0 * x0.x; a0.y += v0 * x0.y; a0.z += v0 * x0.z; a0.w += v0 * x0.w;
        a1.x += v1 * x1.x; a1.y += v1 * x1.y; a1.z += v1 * x1.z; a1.w += v1 * x1.w;
        a2.x += v2 * x2.x; a2.y += v2 * x2.y; a2.z += v2 * x2.z; a2.w += v2 * x2.w;
        a3.x += v3 * x3.x; a3.y += v3 * x3.y; a3.z += v3 * x3.z; a3.w += v3 * x3.w;
    }
    for (; i < e; i++) {
        int2 q0 = g_cv[i];
        float v0 = __int_as_float(q0.y);
        float4 x0 = *reinterpret_cast<const float4*>(egoL + q0.x * DD);
        a0.x += v0 * x0.x; a0.y += v0 * x0.y; a0.z += v0 * x0.z; a0.w += v0 * x0.w;
    }
    a0.x += a1.x; a0.y += a1.y; a0.z += a1.z; a0.w += a1.w;
    a2.x += a3.x; a2.y += a3.y; a2.z += a3.z; a2.w += a3.w;
    a0.x += a2.x; a0.y += a2.y; a0.z += a2.z; a0.w += a2.w;
    *reinterpret_cast<float4*>(g_side + row * DD + lane * 4) = a0;
}

// ---------------- persistent fused layer GEMM --------------------------------
// new_ego = leaky(side @ W1^T + b1) + leaky((ego*side) @ W2^T + b2)
// out[:, (l+1)*128:(l+2)*128] = l2_normalize(new_ego);  g_ego = new_ego
#define BM 64
#define PW 132
#define NTILES ((N_TOT + BM - 1) / BM)     // 2344
#define GRID_GEMM 148
#define GEMM_SMEM ((2 * DD * PW + 2 * BM * PW) * 4)

__global__ void __launch_bounds__(512, 1)
gemm_fused_kernel(const float* __restrict__ W1g,
                  const float* __restrict__ W2g,
                  const float* __restrict__ b1g,
                  const float* __restrict__ b2g,
                  float* __restrict__ out, int layer) {
    extern __shared__ float smem[];
    float* sW1 = smem;                    // [128 j][PW] j-major
    float* sW2 = sW1 + DD * PW;
    float* sS  = sW2 + DD * PW;           // [64 m][PW]
    float* sE  = sS  + BM * PW;
    __shared__ float sRed[16 * 8];        // cross-warp sumsq

    const int t   = threadIdx.x;
    const int cn  = t & 63;
    const int rg  = t >> 6;
    const int wid  = t >> 5;
    const int lane = t & 31;

    // ---- stage weights once ----
    {
        const float* W1 = W1g + layer * DD * DD;
        const float* W2 = W2g + layer * DD * DD;
        for (int i = t; i < DD * 32; i += 512) {
            int j = i >> 5, c = (i & 31) * 4;
            *reinterpret_cast<float4*>(&sW1[j * PW + c]) =
                *reinterpret_cast<const float4*>(W1 + j * DD + c);
            *reinterpret_cast<float4*>(&sW2[j * PW + c]) =
                *reinterpret_cast<const float4*>(W2 + j * DD + c);
        }
    }

    const float bb1a = b1g[layer * DD + cn];
    const float bb1b = b1g[layer * DD + cn + 64];
    const float bb2a = b2g[layer * DD + cn];
    const float bb2b = b2g[layer * DD + cn + 64];

    const int am = t >> 5;                 // 0..15
    const int ac = (t & 31) * 4;           // 0..124

    const float* pS   = &sS[(rg * 8) * PW];
    const float* pE   = &sE[(rg * 8) * PW];
    const float* pW1a = &sW1[cn * PW];
    const float* pW1b = &sW1[(cn + 64) * PW];
    const float* pW2a = &sW2[cn * PW];
    const float* pW2b = &sW2[(cn + 64) * PW];

    float4 s4[4], e4[4];

    int tile = blockIdx.x;
    {
        int base = tile * BM;
#pragma unroll
        for (int rep = 0; rep < 4; rep++) {
            int row = base + am + 16 * rep;
            if (row < N_TOT) {
                s4[rep] = *reinterpret_cast<const float4*>(g_side + row * DD + ac);
                e4[rep] = *reinterpret_cast<const float4*>(g_ego  + row * DD + ac);
            } else {
                s4[rep] = make_float4(0.f, 0.f, 0.f, 0.f);
                e4[rep] = make_float4(0.f, 0.f, 0.f, 0.f);
            }
        }
    }

    while (tile < NTILES) {
        __syncthreads();
#pragma unroll
        for (int rep = 0; rep < 4; rep++) {
            int m = am + 16 * rep;
            float4 sv = s4[rep], ev = e4[rep];
            float4 pv = make_float4(sv.x * ev.x, sv.y * ev.y, sv.z * ev.z, sv.w * ev.w);
            *reinterpret_cast<float4*>(&sS[m * PW + ac]) = sv;
            *reinterpret_cast<float4*>(&sE[m * PW + ac]) = pv;
        }
        __syncthreads();

        const int base = tile * BM;
        const int next = tile + GRID_GEMM;

        if (next < NTILES) {
            int nb = next * BM;
#pragma unroll
            for (int rep = 0; rep < 4; rep++) {
                int row = nb + am + 16 * rep;
                if (row < N_TOT) {
                    s4[rep] = *reinterpret_cast<const float4*>(g_side + row * DD + ac);
                    e4[rep] = *reinterpret_cast<const float4*>(g_ego  + row * DD + ac);
                } else {
                    s4[rep] = make_float4(0.f, 0.f, 0.f, 0.f);
                    e4[rep] = make_float4(0.f, 0.f, 0.f, 0.f);
                }
            }
        }

        unsigned long long acc1[8][2], acc2[8][2];
#pragma unroll
        for (int r = 0; r < 8; r++) {
            acc1[r][0] = 0ull; acc1[r][1] = 0ull;
            acc2[r][0] = 0ull; acc2[r][1] = 0ull;
        }

#pragma unroll 2
        for (int k = 0; k < DD; k += 4) {
            ulonglong2 w1a = *reinterpret_cast<const ulonglong2*>(pW1a + k);
            ulonglong2 w1b = *reinterpret_cast<const ulonglong2*>(pW1b + k);
            ulonglong2 w2a = *reinterpret_cast<const ulonglong2*>(pW2a + k);
            ulonglong2 w2b = *reinterpret_cast<const ulonglong2*>(pW2b + k);
#pragma unroll
            for (int r = 0; r < 8; r++) {
                ulonglong2 aS = *reinterpret_cast<const ulonglong2*>(pS + r * PW + k);
                ulonglong2 aE = *reinterpret_cast<const ulonglong2*>(pE + r * PW + k);
                fma2(acc1[r][0], aS.x, w1a.x); fma2(acc1[r][0], aS.y, w1a.y);
                fma2(acc1[r][1], aS.x, w1b.x); fma2(acc1[r][1], aS.y, w1b.y);
                fma2(acc2[r][0], aE.x, w2a.x); fma2(acc2[r][0], aE.y, w2a.y);
                fma2(acc2[r][1], aE.x, w2b.x); fma2(acc2[r][1], aE.y, w2b.y);
            }
        }

        float oo[8][2];
        float ss[8];
#pragma unroll
        for (int r = 0; r < 8; r++) {
            U64F2 x;
            x.u = acc1[r][0]; float v1a = x.f.x + x.f.y;
            x.u = acc1[r][1]; float v1b = x.f.x + x.f.y;
            x.u = acc2[r][0]; float v2a = x.f.x + x.f.y;
            x.u = acc2[r][1]; float v2b = x.f.x + x.f.y;
            float x1 = v1a + bb1a; x1 = (x1 >= 0.f) ? x1 : NEG_SLOPE * x1;
            float x2 = v2a + bb2a; x2 = (x2 >= 0.f) ? x2 : NEG_SLOPE * x2;
            float y1 = v1b + bb1b; y1 = (y1 >= 0.f) ? y1 : NEG_SLOPE * y1;
            float y2 = v2b + bb2b; y2 = (y2 >= 0.f) ? y2 : NEG_SLOPE * y2;
            float o0 = x1 + x2;
            float o1 = y1 + y2;
            oo[r][0] = o0; oo[r][1] = o1;
            ss[r] = o0 * o0 + o1 * o1;
        }
#pragma unroll
        for (int off = 16; off > 0; off >>= 1) {
#pragma unroll
            for (int r = 0; r < 8; r++)
                ss[r] += __shfl_xor_sync(0xffffffffu, ss[r], off);
        }
        __syncthreads();
        if (lane == 0) {
#pragma unroll
            for (int r = 0; r < 8; r++) sRed[wid * 8 + r] = ss[r];
        }
        __syncthreads();

#pragma unroll
        for (int r = 0; r < 8; r++) {
            float tot = sRed[(2 * rg) * 8 + r] + sRed[(2 * rg + 1) * 8 + r];
            int row = base + rg * 8 + r;
            if (row < N_TOT) {
                float sc = 1.0f / fmaxf(sqrtf(tot), EPSN);
                g_ego[row * DD + cn]      = oo[r][0];
                g_ego[row * DD + cn + 64] = oo[r][1];
                size_t ob = (size_t)row * (4 * DD) + (size_t)(layer + 1) * DD;
                out[ob + cn]      = oo[r][0] * sc;
                out[ob + cn + 64] = oo[r][1] * sc;
            }
        }

        tile = next;
    }
}

// ---------------- launch -----------------------------------------------------
extern "C" void kernel_launch(void* const* d_in, const int* in_sizes, int n_in,
                              void* d_out, int out_size) {
    const float* author = (const float*)d_in[0];
    const float* paper  = (const float*)d_in[1];
    const int*   rows   = (const int*)  d_in[2];
    const int*   cols   = (const int*)  d_in[3];
    const float* vals   = (const float*)d_in[4];
    const float* W1     = (const float*)d_in[5];
    const float* b1     = (const float*)d_in[6];
    const float* W2     = (const float*)d_in[7];
    const float* b2     = (const float*)d_in[8];
    float* out = (float*)d_out;

    cudaFuncSetAttribute(gemm_fused_kernel,
                         cudaFuncAttributeMaxDynamicSharedMemorySize, GEMM_SMEM);

    // CSR build (g_cnt is zero on entry: module init on call 1, fill re-zeroes after)
    count_kernel<<<(NEDGE + 255) / 256, 256>>>(rows);
    scan1_kernel<<<NBS, 256>>>();
    scan3_kernel<<<NBS, 256>>>();
    fill_kernel<<<(NEDGE + 255) / 256, 256>>>(rows, cols, vals);
    init_kernel<<<(N_TOT * 32 + 255) / 256, 256>>>(author, paper, out);

    const int spmm_threads = N_TOT * 32;
    for (int l = 0; l < NLAY; l++) {
        spmm_kernel<<<(spmm_threads + 255) / 256, 256>>>();
        gemm_fused_kernel<<<GRID_GEMM, 512, GEMM_SMEM>>>(W1, W2, b1, b2, out, l);
    }
}

// round 11
// speedup vs baseline: 1.0335x; 1.0335x over previous
#include <cuda_runtime.h>
#include <math.h>

#define N_AUTH  50000
#define N_PAP   100000
#define N_TOT   150000
#define DD      128
#define NLAY    3
#define NEDGE   2400000
#define NEG_SLOPE 0.01f
#define EPSN    1e-12f

#define NBS     293          // scan blocks: ceil(150000/512)
#define SCH     512          // counts per scan block

// ---------------- static device scratch (no runtime alloc allowed) ----------
static __device__ float g_ego [N_TOT * DD];
static __device__ float g_side[N_TOT * DD];
static __device__ int   g_rowptr[N_TOT + 1];
static __device__ int   g_wptr  [N_TOT];
static __device__ int   g_cnt   [N_TOT];     // zero at module load; fill re-zeroes
static __device__ int   g_colv  [NEDGE];
static __device__ float g_valv  [NEDGE];

// ---------------- helpers ----------------------------------------------------
__device__ __forceinline__ void fma2(unsigned long long& d,
                                     unsigned long long a,
                                     unsigned long long b) {
    asm("fma.rn.f32x2 %0, %1, %2, %0;" : "+l"(d) : "l"(a), "l"(b));
}
union U64F2 { unsigned long long u; float2 f; };

// ---------------- CSR build --------------------------------------------------
__global__ void count_kernel(const int* __restrict__ rows) {
    int i = blockIdx.x * blockDim.x + threadIdx.x;
    if (i < NEDGE) atomicAdd(&g_cnt[rows[i]], 1);
}

// single-kernel scan: block b sums g_cnt[0 .. b*512) for its offset, then
// local exclusive scan of its 512 counts.
__global__ void scan_all_kernel() {
    __shared__ int sh[256];
    int b = blockIdx.x, t = threadIdx.x;

    int lim = b * SCH;
    int acc = 0;
    for (int i = t; i < lim; i += 256) acc += g_cnt[i];
    sh[t] = acc;
    __syncthreads();
    for (int o = 128; o > 0; o >>= 1) {
        if (t < o) sh[t] += sh[t + o];
        __syncthreads();
    }
    const int off = sh[0];
    __syncthreads();

    // local scan over pairs
    int i0 = b * SCH + 2 * t;
    int c0 = (i0     < N_TOT) ? g_cnt[i0]     : 0;
    int c1 = (i0 + 1 < N_TOT) ? g_cnt[i0 + 1] : 0;
    int pair = c0 + c1;
    sh[t] = pair;
    __syncthreads();
    for (int o = 1; o < 256; o <<= 1) {
        int x = (t >= o) ? sh[t - o] : 0;
        __syncthreads();
        sh[t] += x;
        __syncthreads();
    }
    int excl = sh[t] - pair + off;
    if (i0 < N_TOT)     { g_rowptr[i0]     = excl;      g_wptr[i0]     = excl; }
    if (i0 + 1 < N_TOT) { g_rowptr[i0 + 1] = excl + c0; g_wptr[i0 + 1] = excl + c0; }
    if (b == NBS - 1 && t == 255) g_rowptr[N_TOT] = off + sh[255];
}

// fill CSR and re-zero g_cnt for the next call
__global__ void fill_kernel(const int* __restrict__ rows,
                            const int* __restrict__ cols,
                            const float* __restrict__ vals) {
    int i = blockIdx.x * blockDim.x + threadIdx.x;
    if (i < N_TOT) g_cnt[i] = 0;
    if (i < NEDGE) {
        int r = rows[i];
        int p = atomicAdd(&g_wptr[r], 1);
        g_colv[p] = cols[i];
        g_valv[p] = vals[i];
    }
}

// ---------------- init -------------------------------------------------------
__global__ void init_kernel(const float* __restrict__ author,
                            const float* __restrict__ paper,
                            float* __restrict__ out) {
    int i = blockIdx.x * blockDim.x + threadIdx.x;
    if (i >= N_TOT * 32) return;
    int node = i >> 5;
    int c4   = (i & 31) * 4;
    float4 v;
    if (node < N_AUTH) v = *reinterpret_cast<const float4*>(author + node * DD + c4);
    else               v = *reinterpret_cast<const float4*>(paper + (node - N_AUTH) * DD + c4);
    *reinterpret_cast<float4*>(g_ego + node * DD + c4) = v;
    *reinterpret_cast<float4*>(out + (size_t)node * (4 * DD) + c4) = v;
}

// ---------------- SpMM: warp per row, 4 dims per lane, unroll-4 --------------
// FIRST: gather straight from author/paper (layer 0, before init runs)
template <bool FIRST>
__device__ __forceinline__ float4 ego_row4(int c, int lane4,
                                           const float* __restrict__ author,
                                           const float* __restrict__ paper) {
    if (FIRST) {
        const float* p = (c < N_AUTH) ? (author + (size_t)c * DD)
                                      : (paper + (size_t)(c - N_AUTH) * DD);
        return *reinterpret_cast<const float4*>(p + lane4);
    }
    return *reinterpret_cast<const float4*>(g_ego + (size_t)c * DD + lane4);
}

template <bool FIRST>
__global__ void spmm_kernel(const float* __restrict__ author,
                            const float* __restrict__ paper) {
    int gt   = blockIdx.x * blockDim.x + threadIdx.x;
    int row  = gt >> 5;
    int lane = gt & 31;
    if (row >= N_TOT) return;
    int s = g_rowptr[row];
    int e = g_rowptr[row + 1];
    const int lane4 = lane * 4;
    float4 a0 = make_float4(0.f, 0.f, 0.f, 0.f);
    float4 a1 = make_float4(0.f, 0.f, 0.f, 0.f);
    int i = s;
    for (; i + 3 < e; i += 4) {
        int   c0 = g_colv[i];
        int   c1 = g_colv[i + 1];
        int   c2 = g_colv[i + 2];
        int   c3 = g_colv[i + 3];
        float v0 = g_valv[i];
        float v1 = g_valv[i + 1];
        float v2 = g_valv[i + 2];
        float v3 = g_valv[i + 3];
        float4 x0 = ego_row4<FIRST>(c0, lane4, author, paper);
        float4 x1 = ego_row4<FIRST>(c1, lane4, author, paper);
        float4 x2 = ego_row4<FIRST>(c2, lane4, author, paper);
        float4 x3 = ego_row4<FIRST>(c3, lane4, author, paper);
        a0.x += v0 * x0.x; a0.y += v0 * x0.y; a0.z += v0 * x0.z; a0.w += v0 * x0.w;
        a1.x += v1 * x1.x; a1.y += v1 * x1.y; a1.z += v1 * x1.z; a1.w += v1 * x1.w;
        a0.x += v2 * x2.x; a0.y += v2 * x2.y; a0.z += v2 * x2.z; a0.w += v2 * x2.w;
        a1.x += v3 * x3.x; a1.y += v3 * x3.y; a1.z += v3 * x3.z; a1.w += v3 * x3.w;
    }
    for (; i < e; i++) {
        int   c0 = g_colv[i];
        float v0 = g_valv[i];
        float4 x0 = ego_row4<FIRST>(c0, lane4, author, paper);
        a0.x += v0 * x0.x; a0.y += v0 * x0.y; a0.z += v0 * x0.z; a0.w += v0 * x0.w;
    }
    a0.x += a1.x; a0.y += a1.y; a0.z += a1.z; a0.w += a1.w;
    *reinterpret_cast<float4*>(g_side + row * DD + lane4) = a0;
}

// ---------------- persistent fused layer GEMM --------------------------------
// new_ego = leaky(side @ W1^T + b1) + leaky((ego*side) @ W2^T + b2)
// out[:, (l+1)*128:(l+2)*128] = l2_normalize(new_ego);  g_ego = new_ego
#define BM 64
#define PW 132
#define NTILES ((N_TOT + BM - 1) / BM)     // 2344
#define GRID_GEMM 148
#define GEMM_SMEM ((2 * DD * PW + 2 * BM * PW) * 4)

__global__ void __launch_bounds__(512, 1)
gemm_fused_kernel(const float* __restrict__ W1g,
                  const float* __restrict__ W2g,
                  const float* __restrict__ b1g,
                  const float* __restrict__ b2g,
                  float* __restrict__ out, int layer) {
    extern __shared__ float smem[];
    float* sW1 = smem;                    // [128 j][PW] j-major
    float* sW2 = sW1 + DD * PW;
    float* sS  = sW2 + DD * PW;           // [64 m][PW]
    float* sE  = sS  + BM * PW;
    __shared__ float sRed[16 * 8];        // cross-warp sumsq

    const int t   = threadIdx.x;
    const int cn  = t & 63;
    const int rg  = t >> 6;
    const int wid  = t >> 5;
    const int lane = t & 31;

    // ---- stage weights once ----
    {
        const float* W1 = W1g + layer * DD * DD;
        const float* W2 = W2g + layer * DD * DD;
        for (int i = t; i < DD * 32; i += 512) {
            int j = i >> 5, c = (i & 31) * 4;
            *reinterpret_cast<float4*>(&sW1[j * PW + c]) =
                *reinterpret_cast<const float4*>(W1 + j * DD + c);
            *reinterpret_cast<float4*>(&sW2[j * PW + c]) =
                *reinterpret_cast<const float4*>(W2 + j * DD + c);
        }
    }

    const float bb1a = b1g[layer * DD + cn];
    const float bb1b = b1g[layer * DD + cn + 64];
    const float bb2a = b2g[layer * DD + cn];
    const float bb2b = b2g[layer * DD + cn + 64];

    const int am = t >> 5;                 // 0..15
    const int ac = (t & 31) * 4;           // 0..124

    const float* pS   = &sS[(rg * 8) * PW];
    const float* pE   = &sE[(rg * 8) * PW];
    const float* pW1a = &sW1[cn * PW];
    const float* pW1b = &sW1[(cn + 64) * PW];
    const float* pW2a = &sW2[cn * PW];
    const float* pW2b = &sW2[(cn + 64) * PW];

    float4 s4[4], e4[4];

    int tile = blockIdx.x;
    {
        int base = tile * BM;
#pragma unroll
        for (int rep = 0; rep < 4; rep++) {
            int row = base + am + 16 * rep;
            if (row < N_TOT) {
                s4[rep] = *reinterpret_cast<const float4*>(g_side + row * DD + ac);
                e4[rep] = *reinterpret_cast<const float4*>(g_ego  + row * DD + ac);
            } else {
                s4[rep] = make_float4(0.f, 0.f, 0.f, 0.f);
                e4[rep] = make_float4(0.f, 0.f, 0.f, 0.f);
            }
        }
    }

    while (tile < NTILES) {
        __syncthreads();
#pragma unroll
        for (int rep = 0; rep < 4; rep++) {
            int m = am + 16 * rep;
            float4 sv = s4[rep], ev = e4[rep];
            float4 pv = make_float4(sv.x * ev.x, sv.y * ev.y, sv.z * ev.z, sv.w * ev.w);
            *reinterpret_cast<float4*>(&sS[m * PW + ac]) = sv;
            *reinterpret_cast<float4*>(&sE[m * PW + ac]) = pv;
        }
        __syncthreads();

        const int base = tile * BM;
        const int next = tile + GRID_GEMM;

        if (next < NTILES) {
            int nb = next * BM;
#pragma unroll
            for (int rep = 0; rep < 4; rep++) {
                int row = nb + am + 16 * rep;
                if (row < N_TOT) {
                    s4[rep] = *reinterpret_cast<const float4*>(g_side + row * DD + ac);
                    e4[rep] = *reinterpret_cast<const float4*>(g_ego  + row * DD + ac);
                } else {
                    s4[rep] = make_float4(0.f, 0.f, 0.f, 0.f);
                    e4[rep] = make_float4(0.f, 0.f, 0.f, 0.f);
                }
            }
        }

        unsigned long long acc1[8][2], acc2[8][2];
#pragma unroll
        for (int r = 0; r < 8; r++) {
            acc1[r][0] = 0ull; acc1[r][1] = 0ull;
            acc2[r][0] = 0ull; acc2[r][1] = 0ull;
        }

#pragma unroll 2
        for (int k = 0; k < DD; k += 4) {
            ulonglong2 w1a = *reinterpret_cast<const ulonglong2*>(pW1a + k);
            ulonglong2 w1b = *reinterpret_cast<const ulonglong2*>(pW1b + k);
            ulonglong2 w2a = *reinterpret_cast<const ulonglong2*>(pW2a + k);
            ulonglong2 w2b = *reinterpret_cast<const ulonglong2*>(pW2b + k);
#pragma unroll
            for (int r = 0; r < 8; r++) {
                ulonglong2 aS = *reinterpret_cast<const ulonglong2*>(pS + r * PW + k);
                ulonglong2 aE = *reinterpret_cast<const ulonglong2*>(pE + r * PW + k);
                fma2(acc1[r][0], aS.x, w1a.x); fma2(acc1[r][0], aS.y, w1a.y);
                fma2(acc1[r][1], aS.x, w1b.x); fma2(acc1[r][1], aS.y, w1b.y);
                fma2(acc2[r][0], aE.x, w2a.x); fma2(acc2[r][0], aE.y, w2a.y);
                fma2(acc2[r][1], aE.x, w2b.x); fma2(acc2[r][1], aE.y, w2b.y);
            }
        }

        float oo[8][2];
        float ss[8];
#pragma unroll
        for (int r = 0; r < 8; r++) {
            U64F2 x;
            x.u = acc1[r][0]; float v1a = x.f.x + x.f.y;
            x.u = acc1[r][1]; float v1b = x.f.x + x.f.y;
            x.u = acc2[r][0]; float v2a = x.f.x + x.f.y;
            x.u = acc2[r][1]; float v2b = x.f.x + x.f.y;
            float x1 = v1a + bb1a; x1 = (x1 >= 0.f) ? x1 : NEG_SLOPE * x1;
            float x2 = v2a + bb2a; x2 = (x2 >= 0.f) ? x2 : NEG_SLOPE * x2;
            float y1 = v1b + bb1b; y1 = (y1 >= 0.f) ? y1 : NEG_SLOPE * y1;
            float y2 = v2b + bb2b; y2 = (y2 >= 0.f) ? y2 : NEG_SLOPE * y2;
            float o0 = x1 + x2;
            float o1 = y1 + y2;
            oo[r][0] = o0; oo[r][1] = o1;
            ss[r] = o0 * o0 + o1 * o1;
        }
#pragma unroll
        for (int off = 16; off > 0; off >>= 1) {
#pragma unroll
            for (int r = 0; r < 8; r++)
                ss[r] += __shfl_xor_sync(0xffffffffu, ss[r], off);
        }
        __syncthreads();
        if (lane == 0) {
#pragma unroll
            for (int r = 0; r < 8; r++) sRed[wid * 8 + r] = ss[r];
        }
        __syncthreads();

#pragma unroll
        for (int r = 0; r < 8; r++) {
            float tot = sRed[(2 * rg) * 8 + r] + sRed[(2 * rg + 1) * 8 + r];
            int row = base + rg * 8 + r;
            if (row < N_TOT) {
                float sc = 1.0f / fmaxf(sqrtf(tot), EPSN);
                g_ego[row * DD + cn]      = oo[r][0];
                g_ego[row * DD + cn + 64] = oo[r][1];
                size_t ob = (size_t)row * (4 * DD) + (size_t)(layer + 1) * DD;
                out[ob + cn]      = oo[r][0] * sc;
                out[ob + cn + 64] = oo[r][1] * sc;
            }
        }

        tile = next;
    }
}

// ---------------- launch -----------------------------------------------------
extern "C" void kernel_launch(void* const* d_in, const int* in_sizes, int n_in,
                              void* d_out, int out_size) {
    const float* author = (const float*)d_in[0];
    const float* paper  = (const float*)d_in[1];
    const int*   rows   = (const int*)  d_in[2];
    const int*   cols   = (const int*)  d_in[3];
    const float* vals   = (const float*)d_in[4];
    const float* W1     = (const float*)d_in[5];
    const float* b1     = (const float*)d_in[6];
    const float* W2     = (const float*)d_in[7];
    const float* b2     = (const float*)d_in[8];
    float* out = (float*)d_out;

    cudaFuncSetAttribute(gemm_fused_kernel,
                         cudaFuncAttributeMaxDynamicSharedMemorySize, GEMM_SMEM);

    const int spmm_threads = N_TOT * 32;

    // CSR build; layer-0 SpMM is launch #4 (profiler slot), reading raw inputs
    count_kernel<<<(NEDGE + 255) / 256, 256>>>(rows);
    scan_all_kernel<<<NBS, 256>>>();
    fill_kernel<<<(NEDGE + 255) / 256, 256>>>(rows, cols, vals);
    spmm_kernel<true><<<(spmm_threads + 255) / 256, 256>>>(author, paper);
    init_kernel<<<(N_TOT * 32 + 255) / 256, 256>>>(author, paper, out);
    gemm_fused_kernel<<<GRID_GEMM, 512, GEMM_SMEM>>>(W1, W2, b1, b2, out, 0);

    for (int l = 1; l < NLAY; l++) {
        spmm_kernel<false><<<(spmm_threads + 255) / 256, 256>>>(author, paper);
        gemm_fused_kernel<<<GRID_GEMM, 512, GEMM_SMEM>>>(W1, W2, b1, b2, out, l);
    }
}

// round 17
// speedup vs baseline: 1.1764x; 1.1383x over previous
#include <cuda_runtime.h>
#include <cuda_bf16.h>
#include <math.h>
#include <stdint.h>

#define N_AUTH  50000
#define N_PAP   100000
#define N_TOT   150000
#define DD      128
#define NLAY    3
#define NEDGE   2400000
#define NEG_SLOPE 0.01f
#define EPSN    1e-12f

#define NBS     293
#define SCH     512

// ---------------- static device scratch --------------------------------------
static __device__ float g_ego [N_TOT * DD];
static __device__ float g_side[N_TOT * DD];
static __device__ int   g_rowptr[N_TOT + 1];
static __device__ int   g_wptr  [N_TOT];
static __device__ int   g_cnt   [N_TOT];
static __device__ int   g_colv  [NEDGE];
static __device__ float g_valv  [NEDGE];

// ---------------- mma/ldmatrix helpers (R15-proven asm style) ----------------
__device__ __forceinline__ uint32_t smem_u32(const void* p) {
    uint32_t a;
    asm("{ .reg .u64 t; cvta.to.shared.u64 t, %1; cvt.u32.u64 %0, t; }"
        : "=r"(a) : "l"(p));
    return a;
}

__device__ __forceinline__ void ldsm4(uint32_t* r, uint32_t addr) {
    uint32_t a0, a1, a2, a3;
    asm volatile("ldmatrix.sync.aligned.m8n8.x4.shared.b16 {%0, %1, %2, %3}, [%4];"
                 : "=r"(a0), "=r"(a1), "=r"(a2), "=r"(a3) : "r"(addr));
    r[0] = a0; r[1] = a1; r[2] = a2; r[3] = a3;
}

__device__ __forceinline__ void mma_bf16(float* c,
                                         uint32_t a0, uint32_t a1, uint32_t a2, uint32_t a3,
                                         uint32_t b0, uint32_t b1) {
    float d0 = c[0];
    float d1 = c[1];
    float d2 = c[2];
    float d3 = c[3];
    asm volatile("mma.sync.aligned.m16n8k16.row.col.f32.bf16.bf16.f32 {%0, %1, %2, %3}, {%4, %5, %6, %7}, {%8, %9}, {%0, %1, %2, %3};"
                 : "+f"(d0), "+f"(d1), "+f"(d2), "+f"(d3)
                 : "r"(a0), "r"(a1), "r"(a2), "r"(a3), "r"(b0), "r"(b1));
    c[0] = d0; c[1] = d1; c[2] = d2; c[3] = d3;
}

__device__ __forceinline__ uint32_t pack_bf2(__nv_bfloat16 a, __nv_bfloat16 b) {
    uint32_t lo = (uint32_t)__bfloat16_as_ushort(a);
    uint32_t hi = (uint32_t)__bfloat16_as_ushort(b);
    return lo | (hi << 16);
}

// ---------------- CSR build --------------------------------------------------
__global__ void count_kernel(const int* __restrict__ rows) {
    int i = blockIdx.x * blockDim.x + threadIdx.x;
    if (i < NEDGE) atomicAdd(&g_cnt[rows[i]], 1);
}

__global__ void scan_all_kernel() {
    __shared__ int sh[256];
    int b = blockIdx.x, t = threadIdx.x;
    int lim = b * SCH;
    int acc = 0;
    for (int i = t; i < lim; i += 256) acc += g_cnt[i];
    sh[t] = acc;
    __syncthreads();
    for (int o = 128; o > 0; o >>= 1) {
        if (t < o) sh[t] += sh[t + o];
        __syncthreads();
    }
    const int off = sh[0];
    __syncthreads();
    int i0 = b * SCH + 2 * t;
    int c0 = (i0     < N_TOT) ? g_cnt[i0]     : 0;
    int c1 = (i0 + 1 < N_TOT) ? g_cnt[i0 + 1] : 0;
    int pair = c0 + c1;
    sh[t] = pair;
    __syncthreads();
    for (int o = 1; o < 256; o <<= 1) {
        int x = (t >= o) ? sh[t - o] : 0;
        __syncthreads();
        sh[t] += x;
        __syncthreads();
    }
    int excl = sh[t] - pair + off;
    if (i0 < N_TOT)     { g_rowptr[i0]     = excl;      g_wptr[i0]     = excl; }
    if (i0 + 1 < N_TOT) { g_rowptr[i0 + 1] = excl + c0; g_wptr[i0 + 1] = excl + c0; }
    if (b == NBS - 1 && t == 255) g_rowptr[N_TOT] = off + sh[255];
}

__global__ void fill_kernel(const int* __restrict__ rows,
                            const int* __restrict__ cols,
                            const float* __restrict__ vals) {
    int i = blockIdx.x * blockDim.x + threadIdx.x;
    if (i < N_TOT) g_cnt[i] = 0;
    if (i < NEDGE) {
        int r = rows[i];
        int p = atomicAdd(&g_wptr[r], 1);
        g_colv[p] = cols[i];
        g_valv[p] = vals[i];
    }
}

// ---------------- init -------------------------------------------------------
__global__ void init_kernel(const float* __restrict__ author,
                            const float* __restrict__ paper,
                            float* __restrict__ out) {
    int i = blockIdx.x * blockDim.x + threadIdx.x;
    if (i >= N_TOT * 32) return;
    int node = i >> 5;
    int c4   = (i & 31) * 4;
    float4 v;
    if (node < N_AUTH) v = *reinterpret_cast<const float4*>(author + node * DD + c4);
    else               v = *reinterpret_cast<const float4*>(paper + (node - N_AUTH) * DD + c4);
    *reinterpret_cast<float4*>(g_ego + node * DD + c4) = v;
    *reinterpret_cast<float4*>(out + (size_t)node * (4 * DD) + c4) = v;
}

// ---------------- SpMM (identical to R11, measured near floor) ---------------
template <bool FIRST>
__device__ __forceinline__ float4 ego_row4(int c, int lane4,
                                           const float* __restrict__ author,
                                           const float* __restrict__ paper) {
    if (FIRST) {
        const float* p = (c < N_AUTH) ? (author + (size_t)c * DD)
                                      : (paper + (size_t)(c - N_AUTH) * DD);
        return *reinterpret_cast<const float4*>(p + lane4);
    }
    return *reinterpret_cast<const float4*>(g_ego + (size_t)c * DD + lane4);
}

template <bool FIRST>
__global__ void spmm_kernel(const float* __restrict__ author,
                            const float* __restrict__ paper) {
    int gt   = blockIdx.x * blockDim.x + threadIdx.x;
    int row  = gt >> 5;
    int lane = gt & 31;
    if (row >= N_TOT) return;
    int s = g_rowptr[row];
    int e = g_rowptr[row + 1];
    const int lane4 = lane * 4;
    float4 a0 = make_float4(0.f, 0.f, 0.f, 0.f);
    float4 a1 = make_float4(0.f, 0.f, 0.f, 0.f);
    int i = s;
    for (; i + 3 < e; i += 4) {
        int   c0 = g_colv[i];
        int   c1 = g_colv[i + 1];
        int   c2 = g_colv[i + 2];
        int   c3 = g_colv[i + 3];
        float v0 = g_valv[i];
        float v1 = g_valv[i + 1];
        float v2 = g_valv[i + 2];
        float v3 = g_valv[i + 3];
        float4 x0 = ego_row4<FIRST>(c0, lane4, author, paper);
        float4 x1 = ego_row4<FIRST>(c1, lane4, author, paper);
        float4 x2 = ego_row4<FIRST>(c2, lane4, author, paper);
        float4 x3 = ego_row4<FIRST>(c3, lane4, author, paper);
        a0.x += v0 * x0.x; a0.y += v0 * x0.y; a0.z += v0 * x0.z; a0.w += v0 * x0.w;
        a1.x += v1 * x1.x; a1.y += v1 * x1.y; a1.z += v1 * x1.z; a1.w += v1 * x1.w;
        a0.x += v2 * x2.x; a0.y += v2 * x2.y; a0.z += v2 * x2.z; a0.w += v2 * x2.w;
        a1.x += v3 * x3.x; a1.y += v3 * x3.y; a1.z += v3 * x3.z; a1.w += v3 * x3.w;
    }
    for (; i < e; i++) {
        int   c0 = g_colv[i];
        float v0 = g_valv[i];
        float4 x0 = ego_row4<FIRST>(c0, lane4, author, paper);
        a0.x += v0 * x0.x; a0.y += v0 * x0.y; a0.z += v0 * x0.z; a0.w += v0 * x0.w;
    }
    a0.x += a1.x; a0.y += a1.y; a0.z += a1.z; a0.w += a1.w;
    *reinterpret_cast<float4*>(g_side + row * DD + lane4) = a0;
}

// ---------------- mma.sync fused layer GEMM (bf16 hi/lo x3 terms) ------------
// D1 = S@W1^T (Shi*W1hi + Shi*W1lo + Slo*W1hi); D2 same with E=ego*side, W2.
// new_ego = leaky(D1+b1) + leaky(D2+b2); out = l2norm(new_ego).
//
// 512 threads = 16 warps: mw = w&3 (16 rows), nw = w>>2 (32 cols).
// A tiles (64 rows) and W (128 rows) in smem as bf16, padded rows of 136 elems.
#define NT64     ((N_TOT + 63) / 64)       // 2344
#define GRID_MM  148
#define LDB      272                       // 136 bf16 * 2 bytes per row
#define SO_B1    0
#define SO_B2    512
#define SO_RED   1024
#define SO_SH    2048
#define SO_SL    (SO_SH + 64 * LDB)        // 19456
#define SO_EH    (SO_SL + 64 * LDB)        // 36864
#define SO_EL    (SO_EH + 64 * LDB)        // 54272
#define SO_W1H   (SO_EL + 64 * LDB)        // 71680
#define SO_W1L   (SO_W1H + 128 * LDB)      // 106496
#define SO_W2H   (SO_W1L + 128 * LDB)      // 141312
#define SO_W2L   (SO_W2H + 128 * LDB)      // 176128
#define MM_SMEM  (SO_W2L + 128 * LDB)      // 210944

__global__ void __launch_bounds__(512, 1)
gemm_mma_kernel(const float* __restrict__ W1g, const float* __restrict__ W2g,
                const float* __restrict__ b1g, const float* __restrict__ b2g,
                float* __restrict__ out, int layer) {
    extern __shared__ char smem[];
    const uint32_t sb = smem_u32(smem);
    float* sb1  = (float*)(smem + SO_B1);
    float* sb2  = (float*)(smem + SO_B2);
    float* sRed = (float*)(smem + SO_RED);   // [4 nw][64 rows]

    const int t    = threadIdx.x;
    const int w    = t >> 5;
    const int lane = t & 31;
    const int mw   = w & 3;
    const int nw   = w >> 2;

    // ---- stage biases + W hi/lo (once per block) ----
    if (t < 128) {
        sb1[t] = b1g[layer * DD + t];
        sb2[t] = b2g[layer * DD + t];
    }
    {
        const float* W1 = W1g + layer * DD * DD;
        const float* W2 = W2g + layer * DD * DD;
        for (int i = t; i < 2048; i += 512) {
            int j = i >> 4;
            int d = (i & 15) * 8;
            uint32_t doff = (uint32_t)(j * LDB + d * 2);
            float4 f0 = *reinterpret_cast<const float4*>(W1 + j * DD + d);
            float4 f1 = *reinterpret_cast<const float4*>(W1 + j * DD + d + 4);
            float vv[8];
            vv[0] = f0.x; vv[1] = f0.y; vv[2] = f0.z; vv[3] = f0.w;
            vv[4] = f1.x; vv[5] = f1.y; vv[6] = f1.z; vv[7] = f1.w;
            uint32_t ph[4], pl[4];
            for (int p = 0; p < 4; p++) {
                float x = vv[2 * p];
                float y = vv[2 * p + 1];
                __nv_bfloat16 hx = __float2bfloat16(x);
                __nv_bfloat16 hy = __float2bfloat16(y);
                ph[p] = pack_bf2(hx, hy);
                pl[p] = pack_bf2(__float2bfloat16(x - __bfloat162float(hx)),
                                 __float2bfloat16(y - __bfloat162float(hy)));
            }
            *reinterpret_cast<uint4*>(smem + SO_W1H + doff) = make_uint4(ph[0], ph[1], ph[2], ph[3]);
            *reinterpret_cast<uint4*>(smem + SO_W1L + doff) = make_uint4(pl[0], pl[1], pl[2], pl[3]);

            f0 = *reinterpret_cast<const float4*>(W2 + j * DD + d);
            f1 = *reinterpret_cast<const float4*>(W2 + j * DD + d + 4);
            vv[0] = f0.x; vv[1] = f0.y; vv[2] = f0.z; vv[3] = f0.w;
            vv[4] = f1.x; vv[5] = f1.y; vv[6] = f1.z; vv[7] = f1.w;
            for (int p = 0; p < 4; p++) {
                float x = vv[2 * p];
                float y = vv[2 * p + 1];
                __nv_bfloat16 hx = __float2bfloat16(x);
                __nv_bfloat16 hy = __float2bfloat16(y);
                ph[p] = pack_bf2(hx, hy);
                pl[p] = pack_bf2(__float2bfloat16(x - __bfloat162float(hx)),
                                 __float2bfloat16(y - __bfloat162float(hy)));
            }
            *reinterpret_cast<uint4*>(smem + SO_W2H + doff) = make_uint4(ph[0], ph[1], ph[2], ph[3]);
            *reinterpret_cast<uint4*>(smem + SO_W2L + doff) = make_uint4(pl[0], pl[1], pl[2], pl[3]);
        }
    }
    __syncthreads();

    // ldmatrix address offsets (within each matrix half)
    const uint32_t a_off = (uint32_t)((mw * 16 + (lane & 15)) * LDB + (lane >> 4) * 16);
    const uint32_t b_off = (uint32_t)((nw * 32 + (lane & 15)) * LDB + (lane >> 4) * 16);

    // A staging slots: thread t handles row t>>3, k-chunk (t&7)*16
    const int arow = t >> 3;
    const int akb  = (t & 7) * 16;
    const uint32_t adst = (uint32_t)(arow * LDB + akb * 2);

    for (int tile = blockIdx.x; tile < NT64; tile += GRID_MM) {
        // ---- stage A tiles (S, E = ego*side; hi/lo bf16) ----
        {
            int grow = tile * 64 + arow;
            uint32_t shp[8], slp[8], ehp[8], elp[8];
            if (grow < N_TOT) {
                const float* srow = g_side + (size_t)grow * DD + akb;
                const float* erow = g_ego  + (size_t)grow * DD + akb;
                for (int p = 0; p < 8; p++) {
                    float sx = srow[2 * p];
                    float sy = srow[2 * p + 1];
                    float ex = erow[2 * p] * sx;
                    float ey = erow[2 * p + 1] * sy;
                    __nv_bfloat16 hx = __float2bfloat16(sx);
                    __nv_bfloat16 hy = __float2bfloat16(sy);
                    shp[p] = pack_bf2(hx, hy);
                    slp[p] = pack_bf2(__float2bfloat16(sx - __bfloat162float(hx)),
                                      __float2bfloat16(sy - __bfloat162float(hy)));
                    hx = __float2bfloat16(ex);
                    hy = __float2bfloat16(ey);
                    ehp[p] = pack_bf2(hx, hy);
                    elp[p] = pack_bf2(__float2bfloat16(ex - __bfloat162float(hx)),
                                      __float2bfloat16(ey - __bfloat162float(hy)));
                }
            } else {
                for (int p = 0; p < 8; p++) { shp[p] = 0; slp[p] = 0; ehp[p] = 0; elp[p] = 0; }
            }
            *reinterpret_cast<uint4*>(smem + SO_SH + adst)      = make_uint4(shp[0], shp[1], shp[2], shp[3]);
            *reinterpret_cast<uint4*>(smem + SO_SH + adst + 16) = make_uint4(shp[4], shp[5], shp[6], shp[7]);
            *reinterpret_cast<uint4*>(smem + SO_SL + adst)      = make_uint4(slp[0], slp[1], slp[2], slp[3]);
            *reinterpret_cast<uint4*>(smem + SO_SL + adst + 16) = make_uint4(slp[4], slp[5], slp[6], slp[7]);
            *reinterpret_cast<uint4*>(smem + SO_EH + adst)      = make_uint4(ehp[0], ehp[1], ehp[2], ehp[3]);
            *reinterpret_cast<uint4*>(smem + SO_EH + adst + 16) = make_uint4(ehp[4], ehp[5], ehp[6], ehp[7]);
            *reinterpret_cast<uint4*>(smem + SO_EL + adst)      = make_uint4(elp[0], elp[1], elp[2], elp[3]);
            *reinterpret_cast<uint4*>(smem + SO_EL + adst + 16) = make_uint4(elp[4], elp[5], elp[6], elp[7]);
        }
        __syncthreads();

        // ---- k-loop: 8 steps of k16 ----
        float c1[4][4], c2[4][4];
        for (int n = 0; n < 4; n++)
            for (int q = 0; q < 4; q++) { c1[n][q] = 0.f; c2[n][q] = 0.f; }

        for (int kk = 0; kk < 8; kk++) {
            const uint32_t ko = (uint32_t)(kk * 32);
            uint32_t ash[4], asl[4], aeh[4], ael[4];
            ldsm4(ash, sb + SO_SH + a_off + ko);
            ldsm4(asl, sb + SO_SL + a_off + ko);
            ldsm4(aeh, sb + SO_EH + a_off + ko);
            ldsm4(ael, sb + SO_EL + a_off + ko);

            uint32_t bp0[4], bp1[4];
            // W1 hi: terms Shi*W1hi and Slo*W1hi
            ldsm4(bp0, sb + SO_W1H + b_off + ko);
            ldsm4(bp1, sb + SO_W1H + b_off + 16 * LDB + ko);
            mma_bf16(c1[0], ash[0], ash[1], ash[2], ash[3], bp0[0], bp0[2]);
            mma_bf16(c1[1], ash[0], ash[1], ash[2], ash[3], bp0[1], bp0[3]);
            mma_bf16(c1[2], ash[0], ash[1], ash[2], ash[3], bp1[0], bp1[2]);
            mma_bf16(c1[3], ash[0], ash[1], ash[2], ash[3], bp1[1], bp1[3]);
            mma_bf16(c1[0], asl[0], asl[1], asl[2], asl[3], bp0[0], bp0[2]);
            mma_bf16(c1[1], asl[0], asl[1], asl[2], asl[3], bp0[1], bp0[3]);
            mma_bf16(c1[2], asl[0], asl[1], asl[2], asl[3], bp1[0], bp1[2]);
            mma_bf16(c1[3], asl[0], asl[1], asl[2], asl[3], bp1[1], bp1[3]);
            // W1 lo: term Shi*W1lo
            ldsm4(bp0, sb + SO_W1L + b_off + ko);
            ldsm4(bp1, sb + SO_W1L + b_off + 16 * LDB + ko);
            mma_bf16(c1[0], ash[0], ash[1], ash[2], ash[3], bp0[0], bp0[2]);
            mma_bf16(c1[1], ash[0], ash[1], ash[2], ash[3], bp0[1], bp0[3]);
            mma_bf16(c1[2], ash[0], ash[1], ash[2], ash[3], bp1[0], bp1[2]);
            mma_bf16(c1[3], ash[0], ash[1], ash[2], ash[3], bp1[1], bp1[3]);
            // W2 hi: terms Ehi*W2hi and Elo*W2hi
            ldsm4(bp0, sb + SO_W2H + b_off + ko);
            ldsm4(bp1, sb + SO_W2H + b_off + 16 * LDB + ko);
            mma_bf16(c2[0], aeh[0], aeh[1], aeh[2], aeh[3], bp0[0], bp0[2]);
            mma_bf16(c2[1], aeh[0], aeh[1], aeh[2], aeh[3], bp0[1], bp0[3]);
            mma_bf16(c2[2], aeh[0], aeh[1], aeh[2], aeh[3], bp1[0], bp1[2]);
            mma_bf16(c2[3], aeh[0], aeh[1], aeh[2], aeh[3], bp1[1], bp1[3]);
            mma_bf16(c2[0], ael[0], ael[1], ael[2], ael[3], bp0[0], bp0[2]);
            mma_bf16(c2[1], ael[0], ael[1], ael[2], ael[3], bp0[1], bp0[3]);
            mma_bf16(c2[2], ael[0], ael[1], ael[2], ael[3], bp1[0], bp1[2]);
            mma_bf16(c2[3], ael[0], ael[1], ael[2], ael[3], bp1[1], bp1[3]);
            // W2 lo: term Ehi*W2lo
            ldsm4(bp0, sb + SO_W2L + b_off + ko);
            ldsm4(bp1, sb + SO_W2L + b_off + 16 * LDB + ko);
            mma_bf16(c2[0], aeh[0], aeh[1], aeh[2], aeh[3], bp0[0], bp0[2]);
            mma_bf16(c2[1], aeh[0], aeh[1], aeh[2], aeh[3], bp0[1], bp0[3]);
            mma_bf16(c2[2], aeh[0], aeh[1], aeh[2], aeh[3], bp1[0], bp1[2]);
            mma_bf16(c2[3], aeh[0], aeh[1], aeh[2], aeh[3], bp1[1], bp1[3]);
        }

        // ---- epilogue ----
        // C frag: c[q]: q0,q1 = row lane/4, cols 2*(lane%4)+0/1; q2,q3 = row+8
        float o[4][4];
        float ssq0 = 0.f, ssq1 = 0.f;
        const int colb = nw * 32 + (lane & 3) * 2;
        for (int n = 0; n < 4; n++) {
            int cA = colb + n * 8;
            float b1A = sb1[cA];
            float b1B = sb1[cA + 1];
            float b2A = sb2[cA];
            float b2B = sb2[cA + 1];
            for (int q = 0; q < 4; q++) {
                float bb1 = (q & 1) ? b1B : b1A;
                float bb2 = (q & 1) ? b2B : b2A;
                float x1 = c1[n][q] + bb1;
                x1 = (x1 >= 0.f) ? x1 : NEG_SLOPE * x1;
                float x2 = c2[n][q] + bb2;
                x2 = (x2 >= 0.f) ? x2 : NEG_SLOPE * x2;
                float ov = x1 + x2;
                o[n][q] = ov;
                if (q < 2) ssq0 += ov * ov;
                else       ssq1 += ov * ov;
            }
        }
        ssq0 += __shfl_xor_sync(0xffffffffu, ssq0, 1);
        ssq0 += __shfl_xor_sync(0xffffffffu, ssq0, 2);
        ssq1 += __shfl_xor_sync(0xffffffffu, ssq1, 1);
        ssq1 += __shfl_xor_sync(0xffffffffu, ssq1, 2);

        const int lrow0 = mw * 16 + (lane >> 2);
        if ((lane & 3) == 0) {
            sRed[nw * 64 + lrow0]     = ssq0;
            sRed[nw * 64 + lrow0 + 8] = ssq1;
        }
        __syncthreads();
        float tot0 = sRed[lrow0] + sRed[64 + lrow0] + sRed[128 + lrow0] + sRed[192 + lrow0];
        float tot1 = sRed[lrow0 + 8] + sRed[64 + lrow0 + 8] + sRed[128 + lrow0 + 8] + sRed[192 + lrow0 + 8];

        const int grow0 = tile * 64 + lrow0;
        const int grow1 = grow0 + 8;
        const size_t obase = (size_t)(layer + 1) * DD;
        if (grow0 < N_TOT) {
            float sc = 1.0f / fmaxf(sqrtf(tot0), EPSN);
            float* ge = g_ego + (size_t)grow0 * DD;
            float* po = out + (size_t)grow0 * (4 * DD) + obase;
            for (int n = 0; n < 4; n++) {
                int cc = colb + n * 8;
                *reinterpret_cast<float2*>(ge + cc) = make_float2(o[n][0], o[n][1]);
                *reinterpret_cast<float2*>(po + cc) = make_float2(o[n][0] * sc, o[n][1] * sc);
            }
        }
        if (grow1 < N_TOT) {
            float sc = 1.0f / fmaxf(sqrtf(tot1), EPSN);
            float* ge = g_ego + (size_t)grow1 * DD;
            float* po = out + (size_t)grow1 * (4 * DD) + obase;
            for (int n = 0; n < 4; n++) {
                int cc = colb + n * 8;
                *reinterpret_cast<float2*>(ge + cc) = make_float2(o[n][2], o[n][3]);
                *reinterpret_cast<float2*>(po + cc) = make_float2(o[n][2] * sc, o[n][3] * sc);
            }
        }
        __syncthreads();
    }
}

// ---------------- launch -----------------------------------------------------
extern "C" void kernel_launch(void* const* d_in, const int* in_sizes, int n_in,
                              void* d_out, int out_size) {
    const float* author = (const float*)d_in[0];
    const float* paper  = (const float*)d_in[1];
    const int*   rows   = (const int*)  d_in[2];
    const int*   cols   = (const int*)  d_in[3];
    const float* vals   = (const float*)d_in[4];
    const float* W1     = (const float*)d_in[5];
    const float* b1     = (const float*)d_in[6];
    const float* W2     = (const float*)d_in[7];
    const float* b2     = (const float*)d_in[8];
    float* out = (float*)d_out;

    cudaFuncSetAttribute(gemm_mma_kernel,
                         cudaFuncAttributeMaxDynamicSharedMemorySize, MM_SMEM);

    const int spmm_threads = N_TOT * 32;

    count_kernel<<<(NEDGE + 255) / 256, 256>>>(rows);
    scan_all_kernel<<<NBS, 256>>>();
    fill_kernel<<<(NEDGE + 255) / 256, 256>>>(rows, cols, vals);
    spmm_kernel<true><<<(spmm_threads + 255) / 256, 256>>>(author, paper);
    init_kernel<<<(N_TOT * 32 + 255) / 256, 256>>>(author, paper, out);
    gemm_mma_kernel<<<GRID_MM, 512, MM_SMEM>>>(W1, W2, b1, b2, out, 0);

    for (int l = 1; l < NLAY; l++) {
        spmm_kernel<false><<<(spmm_threads + 255) / 256, 256>>>(author, paper);
        gemm_mma_kernel<<<GRID_MM, 512, MM_SMEM>>>(W1, W2, b1, b2, out, l);
    }
}